// round 1
// baseline (speedup 1.0000x reference)
#include <cuda_runtime.h>

#define FULLMASK 0xFFFFFFFFu
constexpr int Bb = 4, Nn = 384, Dd = 64;

__device__ __forceinline__ float wred(float v) {
  #pragma unroll
  for (int o = 16; o > 0; o >>= 1) v += __shfl_xor_sync(FULLMASK, v, o);
  return v;
}
__device__ __forceinline__ float sigm(float x) { return 1.f / (1.f + __expf(-x)); }
__device__ __forceinline__ float silu_(float x) { return x * sigm(x); }
__device__ __forceinline__ float artanh_(float x) {
  x = fminf(x, 1.f - 1e-7f);
  return 0.5f * (log1pf(x) - log1pf(-x));
}

__global__ __launch_bounds__(256, 4)
void hypagg_kernel(const float* __restrict__ x,
                   const int* __restrict__ mask,
                   const float* __restrict__ att_w1,
                   const float* __restrict__ att_b1,
                   const float* __restrict__ att_w2,
                   const float* __restrict__ att_b2,
                   const float* __restrict__ mlp_w1,
                   const float* __restrict__ mlp_b1,
                   const float* __restrict__ mlp_w2,
                   const float* __restrict__ mlp_b2,
                   float* __restrict__ out)
{
  __shared__ __align__(16) float w1s[64 * 64];      // att_w1 rows 0..63 (d-major)
  __shared__ __align__(16) float ubuf[8][64 * 4];   // per-warp 4-edge u staging [d][e]
  __shared__ float w2s[64], xi[64], uself[64], ci[64];
  __shared__ float supp[8][64];
  __shared__ float sup[64], hm[64], ot[64];
  __shared__ float sh_x2i, sh_fac;

  const int tid = threadIdx.x, w = tid >> 5, lane = tid & 31;
  const int bi = blockIdx.x;
  const int b = bi / Nn, i = bi % Nn;
  const float* xrow = x + (size_t)(b * Nn + i) * Dd;
  const float* xb = x + (size_t)b * Nn * Dd;

  // Stage weights + x_i into shared
  for (int t = tid; t < 64 * 64 / 4; t += 256)
    ((float4*)w1s)[t] = ((const float4*)att_w1)[t];
  if (tid < 64) { xi[tid] = xrow[tid]; w2s[tid] = att_w2[tid]; }
  __syncthreads();

  // warp 0: |x_i|^2 and u_self = logmap_{x_i}(x_i)  (tiny but computed like ref)
  if (w == 0) {
    float a0 = xi[lane], a1 = xi[lane + 32];
    float x2i = wred(a0 * a0 + a1 * a1);
    float A = 1.f - 2.f * x2i + x2i;
    float Bc = 1.f - x2i;
    float den = fmaxf(1.f - 2.f * x2i + x2i * x2i, 1e-15f);
    float inv = 1.f / den;
    float s0 = (A * (-a0) + Bc * a0) * inv;
    float s1 = (A * (-a1) + Bc * a1) * inv;
    float sn = fmaxf(sqrtf(wred(s0 * s0 + s1 * s1)), 1e-15f);
    float fac = fmaxf(Bc, 1e-15f);          // 2/lam
    float g = fac * artanh_(sn) / sn;
    uself[lane] = g * s0;
    uself[lane + 32] = g * s1;
    if (lane == 0) { sh_x2i = x2i; sh_fac = fac; }
  }
  __syncthreads();

  // ci[k] = att_b1[k] + u_self . att_w1[64:,k]   (constant per row i)
  if (tid < 64) {
    float acc = att_b1[tid];
    #pragma unroll 8
    for (int d = 0; d < 64; ++d)
      acc = fmaf(uself[d], att_w1[(64 + d) * 64 + tid], acc);
    ci[tid] = acc;
  }
  __syncthreads();

  const float x2i = sh_x2i, fac_i = sh_fac;
  const float a0 = xi[lane], a1 = xi[lane + 32];
  const float b2v = att_b2[0];
  const float cik0 = ci[lane], cik1 = ci[lane + 32];
  const float omx2 = 1.f - x2i;

  // deterministic unmasked-j list for this warp (j == w mod 8), as 48-bit mask
  const int* mrow = mask + (size_t)(b * Nn + i) * Nn;
  unsigned ma = __ballot_sync(FULLMASK, mrow[w + 8 * lane] != 0);
  int mbv = (lane < 16) ? mrow[w + 8 * (32 + lane)] : 0;
  unsigned mb = __ballot_sync(FULLMASK, mbv != 0);
  unsigned long long bits =
      (unsigned long long)ma | ((unsigned long long)(mb & 0xFFFFu) << 32);

  float sup0 = 0.f, sup1 = 0.f;
  float* ubw = &ubuf[w][0];

  while (bits) {
    int js[4]; int ne = 0;
    while (bits && ne < 4) {
      int t = __ffsll((long long)bits) - 1;
      bits &= bits - 1ull;
      js[ne++] = w + 8 * t;
    }
    float ur0[4], ur1[4];
    #pragma unroll
    for (int e = 0; e < 4; ++e) {
      float u0 = 0.f, u1 = 0.f;
      if (e < ne) {
        const float* yr = xb + (size_t)js[e] * Dd;
        float y0 = yr[lane], y1 = yr[lane + 32];
        float xy = wred(a0 * y0 + a1 * y1);
        float y2 = wred(y0 * y0 + y1 * y1);
        float A = 1.f - 2.f * xy + y2;
        float den = fmaxf(1.f - 2.f * xy + x2i * y2, 1e-15f);
        float inv = 1.f / den;
        float s0 = (A * (-a0) + omx2 * y0) * inv;
        float s1 = (A * (-a1) + omx2 * y1) * inv;
        float sn = fmaxf(sqrtf(wred(s0 * s0 + s1 * s1)), 1e-15f);
        float g = fac_i * artanh_(sn) / sn;
        u0 = fminf(fmaxf(g * s0, -1000.f), 1000.f);
        u1 = fminf(fmaxf(g * s1, -1000.f), 1000.f);
      }
      ur0[e] = u0; ur1[e] = u1;
      ubw[lane * 4 + e] = u0;
      ubw[(lane + 32) * 4 + e] = u1;
    }
    __syncwarp();

    // 4-edge batched matvec: h[k] over k = lane, lane+32
    float acc0[4] = {cik0, cik0, cik0, cik0};
    float acc1[4] = {cik1, cik1, cik1, cik1};
    const float4* uv = (const float4*)ubw;
    #pragma unroll 16
    for (int d = 0; d < 64; ++d) {
      float4 uq = uv[d];                     // broadcast: u of 4 edges at dim d
      float wa = w1s[d * 64 + lane];
      float wb = w1s[d * 64 + lane + 32];
      acc0[0] = fmaf(uq.x, wa, acc0[0]);
      acc0[1] = fmaf(uq.y, wa, acc0[1]);
      acc0[2] = fmaf(uq.z, wa, acc0[2]);
      acc0[3] = fmaf(uq.w, wa, acc0[3]);
      acc1[0] = fmaf(uq.x, wb, acc1[0]);
      acc1[1] = fmaf(uq.y, wb, acc1[1]);
      acc1[2] = fmaf(uq.z, wb, acc1[2]);
      acc1[3] = fmaf(uq.w, wb, acc1[3]);
    }
    __syncwarp();

    #pragma unroll
    for (int e = 0; e < 4; ++e) {
      float p = silu_(acc0[e]) * w2s[lane] + silu_(acc1[e]) * w2s[lane + 32];
      p = wred(p);
      if (e < ne) {
        float att = sigm(p + b2v);
        sup0 = fmaf(att, ur0[e], sup0);
        sup1 = fmaf(att, ur1[e], sup1);
      }
    }
  }

  supp[w][lane] = sup0;
  supp[w][lane + 32] = sup1;
  __syncthreads();

  // fixed-order cross-warp reduction of support
  if (tid < 64) {
    float s = 0.f;
    #pragma unroll
    for (int ww = 0; ww < 8; ++ww) s += supp[ww][tid];
    sup[tid] = s;
  }
  __syncthreads();

  // node MLP: silu([u_self, support] @ mlp_w1 + b1) @ mlp_w2 + b2 + u_self
  if (tid < 64) {
    float acc = mlp_b1[tid];
    #pragma unroll 8
    for (int d = 0; d < 64; ++d) acc = fmaf(uself[d], mlp_w1[d * 64 + tid], acc);
    #pragma unroll 8
    for (int d = 0; d < 64; ++d) acc = fmaf(sup[d], mlp_w1[(64 + d) * 64 + tid], acc);
    hm[tid] = silu_(acc);
  }
  __syncthreads();
  if (tid < 64) {
    float o = mlp_b2[tid] + uself[tid];
    #pragma unroll 8
    for (int k = 0; k < 64; ++k) o = fmaf(hm[k], mlp_w2[k * 64 + tid], o);
    ot[tid] = o;
  }
  __syncthreads();

  // expmap(out_t, x_i) + proj   (warp 0)
  if (w == 0) {
    float o0 = ot[lane], o1 = ot[lane + 32];
    float un = fmaxf(sqrtf(wred(o0 * o0 + o1 * o1)), 1e-15f);
    float lam = 2.f / fmaxf(1.f - x2i, 1e-15f);
    float th = tanhf(0.5f * lam * un);
    float sc = th / un;
    float sec0 = sc * o0, sec1 = sc * o1;
    float xy = wred(a0 * sec0 + a1 * sec1);
    float y2 = wred(sec0 * sec0 + sec1 * sec1);
    float A = 1.f + 2.f * xy + y2;
    float Bc = 1.f - x2i;
    float den = fmaxf(1.f + 2.f * xy + x2i * y2, 1e-15f);
    float inv = 1.f / den;
    float r0 = (A * a0 + Bc * sec0) * inv;
    float r1 = (A * a1 + Bc * sec1) * inv;
    float nrm = fmaxf(sqrtf(wred(r0 * r0 + r1 * r1)), 1e-15f);
    if (nrm > 0.996f) { float s = 0.996f / nrm; r0 *= s; r1 *= s; }
    float* orow = out + (size_t)(b * Nn + i) * Dd;
    orow[lane] = r0;
    orow[lane + 32] = r1;
  }
}

extern "C" void kernel_launch(void* const* d_in, const int* in_sizes, int n_in,
                              void* d_out, int out_size)
{
  const float* x       = (const float*)d_in[0];
  const int*   mask    = (const int*)d_in[1];
  const float* att_w1  = (const float*)d_in[2];
  const float* att_b1  = (const float*)d_in[3];
  const float* att_w2  = (const float*)d_in[4];
  const float* att_b2  = (const float*)d_in[5];
  const float* mlp_w1  = (const float*)d_in[6];
  const float* mlp_b1  = (const float*)d_in[7];
  const float* mlp_w2  = (const float*)d_in[8];
  const float* mlp_b2  = (const float*)d_in[9];
  float* out = (float*)d_out;

  hypagg_kernel<<<Bb * Nn, 256>>>(x, mask, att_w1, att_b1, att_w2, att_b2,
                                  mlp_w1, mlp_b1, mlp_w2, mlp_b2, out);
}

// round 2
// speedup vs baseline: 1.9024x; 1.9024x over previous
#include <cuda_runtime.h>

#define FULLMASK 0xFFFFFFFFu
constexpr int Bb = 4, Nn = 384, Dd = 64;
constexpr int NR = Bb * Nn;

__device__ float g_y2[NR];
__device__ float g_uself[NR * Dd];
__device__ float g_ci[NR * Dd];
__device__ float g_P[NR * Dd];
__device__ float g_gram[(size_t)Bb * Nn * Nn];

__device__ __forceinline__ float wred(float v) {
  #pragma unroll
  for (int o = 16; o > 0; o >>= 1) v += __shfl_xor_sync(FULLMASK, v, o);
  return v;
}
__device__ __forceinline__ float sigm(float x) { return 1.f / (1.f + __expf(-x)); }
__device__ __forceinline__ float silu_(float x) { return x * sigm(x); }
__device__ __forceinline__ float artanh_(float x) {       // precise (per-row only)
  x = fminf(x, 1.f - 1e-7f);
  return 0.5f * (log1pf(x) - log1pf(-x));
}

// ---------------- K1a: per-row precompute: y2, uself, P, ci ----------------
__global__ __launch_bounds__(64)
void k_row(const float* __restrict__ x,
           const float* __restrict__ att_w1,
           const float* __restrict__ att_b1)
{
  __shared__ float xi[64], us[64], red[64];
  __shared__ float shx2, shsn2;
  const int tid = threadIdx.x;
  const int row = blockIdx.x;
  xi[tid] = x[(size_t)row * 64 + tid];
  __syncthreads();
  red[tid] = xi[tid] * xi[tid];
  __syncthreads();
  if (tid < 32) { float v = red[tid] + red[tid + 32]; v = wred(v); if (!tid) shx2 = v; }
  __syncthreads();
  const float x2 = shx2;
  // u_self = logmap_{x}(x): same numeric recipe as reference (tiny nonzero)
  const float A = 1.f - 2.f * x2 + x2;
  const float Bc = 1.f - x2;
  const float den = fmaxf(1.f - 2.f * x2 + x2 * x2, 1e-15f);
  const float inv = 1.f / den;
  const float s = (A * (-xi[tid]) + Bc * xi[tid]) * inv;
  red[tid] = s * s;
  __syncthreads();
  if (tid < 32) { float v = red[tid] + red[tid + 32]; v = wred(v); if (!tid) shsn2 = v; }
  __syncthreads();
  const float sn = fmaxf(sqrtf(shsn2), 1e-15f);
  const float fac = fmaxf(Bc, 1e-15f);
  const float g = fac * artanh_(sn) / sn;
  const float u = g * s;
  us[tid] = u;
  g_uself[(size_t)row * 64 + tid] = u;
  if (!tid) g_y2[row] = x2;
  __syncthreads();
  float accP = 0.f, accC = att_b1[tid];
  #pragma unroll 8
  for (int d = 0; d < 64; ++d) {
    accP = fmaf(xi[d], att_w1[d * 64 + tid], accP);
    accC = fmaf(us[d], att_w1[(64 + d) * 64 + tid], accC);
  }
  g_P[(size_t)row * 64 + tid] = accP;
  g_ci[(size_t)row * 64 + tid] = accC;
}

// ---------------- K1b: Gram matrix xy[b][i][j] ----------------
__global__ __launch_bounds__(256)
void k_gram(const float* __restrict__ x)
{
  __shared__ float xis[8][64];
  __shared__ float xjs[32][65];   // pad 65 -> conflict-free column reads
  const int tid = threadIdx.x;
  const int ct = blockIdx.x;
  const int b = ct / 48, i0 = (ct % 48) * 8;
  const float* xb = x + (size_t)b * Nn * 64;
  for (int t = tid; t < 8 * 64; t += 256)
    xis[t >> 6][t & 63] = xb[(size_t)(i0 + (t >> 6)) * 64 + (t & 63)];
  const int ii = tid >> 5, jj = tid & 31;
  for (int jt = 0; jt < 12; ++jt) {
    __syncthreads();
    for (int t = tid; t < 32 * 64; t += 256)
      xjs[t >> 6][t & 63] = xb[(size_t)(jt * 32 + (t >> 6)) * 64 + (t & 63)];
    __syncthreads();
    float acc = 0.f;
    #pragma unroll 16
    for (int d = 0; d < 64; ++d) acc = fmaf(xis[ii][d], xjs[jj][d], acc);
    g_gram[((size_t)(b * Nn) + i0 + ii) * Nn + jt * 32 + jj] = acc;
  }
}

// ---------------- K2: main ----------------
__global__ __launch_bounds__(256)
void k_main(const float* __restrict__ x,
            const int* __restrict__ mask,
            const float* __restrict__ att_w2,
            const float* __restrict__ att_b2,
            const float* __restrict__ mlp_w1,
            const float* __restrict__ mlp_b1,
            const float* __restrict__ mlp_w2,
            const float* __restrict__ mlp_b2,
            float* __restrict__ out)
{
  __shared__ float xi[64], Pis[64], cis[64], uss[64], w2s[64];
  __shared__ float wsm[Nn];
  __shared__ float sup4[4][64];
  __shared__ float supv[64], hm[64], ot[64];
  __shared__ float s1p[8];

  const int tid = threadIdx.x, w = tid >> 5, lane = tid & 31;
  const int row = blockIdx.x;
  const int b = row / Nn;

  if (tid < 64) {
    xi[tid]  = x[(size_t)row * 64 + tid];
    Pis[tid] = g_P[(size_t)row * 64 + tid];
    cis[tid] = g_ci[(size_t)row * 64 + tid];
    uss[tid] = g_uself[(size_t)row * 64 + tid];
    w2s[tid] = att_w2[tid];
  }
  for (int t = tid; t < Nn; t += 256) wsm[t] = 0.f;
  if (tid < 8) s1p[tid] = 0.f;
  __syncthreads();

  const float x2i = g_y2[row];
  const float omx2 = 1.f - x2i;
  const float fac = fmaxf(omx2, 1e-15f);
  const float b2v = att_b2[0];
  const float Pi0 = Pis[lane], Pi1 = Pis[lane + 32];
  const float ci0 = cis[lane], ci1 = cis[lane + 32];
  const float w2a = w2s[lane], w2b = w2s[lane + 32];

  const int* mrow = mask + (size_t)row * Nn;
  const float* gr = g_gram + (size_t)row * Nn;
  const float* Pb = g_P + (size_t)(b * Nn) * 64;
  const float* y2b = g_y2 + b * Nn;

  float S1 = 0.f;
  #pragma unroll
  for (int c = 0; c < 2; ++c) {
    const int cnt = c ? 16 : 32;
    const int jb = w * 48 + c * 32;
    const int j = jb + lane;
    float c1v = 0.f, c2v = 0.f;
    bool ok = (lane < cnt) && (mrow[j] != 0);
    if (ok) {
      const float xy = gr[j], y2 = y2b[j];
      const float A = 1.f - 2.f * xy + y2;
      const float den = fmaxf(fmaf(x2i, y2, 1.f - 2.f * xy), 1e-15f);
      const float inv = __frcp_rn(den);
      // sn^2 = inv^2 * (A*(A*x2 - omx2*xy) + omx2*(omx2*y2 - A*xy))
      const float t1 = fmaf(A, x2i, -omx2 * xy);
      const float t2 = fmaf(omx2, y2, -A * xy);
      float sn2 = inv * inv * fmaf(A, t1, omx2 * t2);
      float sn = sqrtf(fmaxf(sn2, 0.f));
      sn = fminf(fmaxf(sn, 1e-15f), 1.f - 1e-7f);
      float aos;  // artanh(sn)/sn
      if (sn > 1e-3f) aos = 0.5f * __logf((1.f + sn) * __frcp_rn(1.f - sn)) / sn;
      else            aos = fmaf(sn * sn, 0.33333334f, 1.f);
      const float gi = fac * aos * inv;
      c1v = -gi * A;
      c2v = gi * omx2;
    }
    unsigned bm = __ballot_sync(FULLMASK, ok);
    while (bm) {
      const int e = __ffs(bm) - 1; bm &= bm - 1;
      const float c1e = __shfl_sync(FULLMASK, c1v, e);
      const float c2e = __shfl_sync(FULLMASK, c2v, e);
      const int je = jb + e;
      const float* Pj = Pb + (size_t)je * 64;
      const float h0 = fmaf(c2e, Pj[lane],      fmaf(c1e, Pi0, ci0));
      const float h1 = fmaf(c2e, Pj[lane + 32], fmaf(c1e, Pi1, ci1));
      float pr = silu_(h0) * w2a;
      pr = fmaf(silu_(h1), w2b, pr);
      pr = wred(pr);
      const float att = sigm(pr + b2v);
      S1 = fmaf(att, c1e, S1);
      if (lane == 0) wsm[je] = att * c2e;
    }
  }
  if (!lane) s1p[w] = S1;
  __syncthreads();

  // support = S1_tot * x_i + sum_j wsm[j] * x_j
  {
    const int d = tid & 63, ch = tid >> 6;
    const float* xb = x + (size_t)(b * Nn) * 64;
    float part = 0.f;
    for (int j = ch * 96; j < (ch + 1) * 96; ++j) {
      const float wj = wsm[j];
      if (wj != 0.f) part = fmaf(wj, xb[(size_t)j * 64 + d], part);
    }
    sup4[ch][d] = part;
  }
  __syncthreads();
  if (tid < 64) {
    float S1t = 0.f;
    #pragma unroll
    for (int ww = 0; ww < 8; ++ww) S1t += s1p[ww];
    supv[tid] = fmaf(S1t, xi[tid],
                     sup4[0][tid] + sup4[1][tid] + sup4[2][tid] + sup4[3][tid]);
  }
  __syncthreads();

  // node MLP: silu([u_self, support] @ W1 + b1) @ W2 + b2 + u_self
  if (tid < 64) {
    float acc = mlp_b1[tid];
    #pragma unroll 8
    for (int d = 0; d < 64; ++d) acc = fmaf(uss[d],  mlp_w1[d * 64 + tid], acc);
    #pragma unroll 8
    for (int d = 0; d < 64; ++d) acc = fmaf(supv[d], mlp_w1[(64 + d) * 64 + tid], acc);
    hm[tid] = silu_(acc);
  }
  __syncthreads();
  if (tid < 64) {
    float o = mlp_b2[tid] + uss[tid];
    #pragma unroll 8
    for (int k = 0; k < 64; ++k) o = fmaf(hm[k], mlp_w2[k * 64 + tid], o);
    ot[tid] = o;
  }
  __syncthreads();

  // expmap(out_t, x_i) + proj  (warp 0)
  if (w == 0) {
    const float a0 = xi[lane], a1 = xi[lane + 32];
    const float o0 = ot[lane], o1 = ot[lane + 32];
    const float un = fmaxf(sqrtf(wred(o0 * o0 + o1 * o1)), 1e-15f);
    const float lam = 2.f / fmaxf(1.f - x2i, 1e-15f);
    const float th = tanhf(0.5f * lam * un);
    const float sc = th / un;
    const float sec0 = sc * o0, sec1 = sc * o1;
    const float xy = wred(a0 * sec0 + a1 * sec1);
    const float y2 = wred(sec0 * sec0 + sec1 * sec1);
    const float A = 1.f + 2.f * xy + y2;
    const float Bc = 1.f - x2i;
    const float den = fmaxf(1.f + 2.f * xy + x2i * y2, 1e-15f);
    const float inv = 1.f / den;
    float r0 = (A * a0 + Bc * sec0) * inv;
    float r1 = (A * a1 + Bc * sec1) * inv;
    const float nrm = fmaxf(sqrtf(wred(r0 * r0 + r1 * r1)), 1e-15f);
    if (nrm > 0.996f) { const float s = 0.996f / nrm; r0 *= s; r1 *= s; }
    float* orow = out + (size_t)row * 64;
    orow[lane] = r0;
    orow[lane + 32] = r1;
  }
}

extern "C" void kernel_launch(void* const* d_in, const int* in_sizes, int n_in,
                              void* d_out, int out_size)
{
  const float* x      = (const float*)d_in[0];
  const int*   mask   = (const int*)d_in[1];
  const float* att_w1 = (const float*)d_in[2];
  const float* att_b1 = (const float*)d_in[3];
  const float* att_w2 = (const float*)d_in[4];
  const float* att_b2 = (const float*)d_in[5];
  const float* mlp_w1 = (const float*)d_in[6];
  const float* mlp_b1 = (const float*)d_in[7];
  const float* mlp_w2 = (const float*)d_in[8];
  const float* mlp_b2 = (const float*)d_in[9];
  float* out = (float*)d_out;

  k_row<<<NR, 64>>>(x, att_w1, att_b1);
  k_gram<<<Bb * (Nn / 8), 256>>>(x);
  k_main<<<NR, 256>>>(x, mask, att_w2, att_b2,
                      mlp_w1, mlp_b1, mlp_w2, mlp_b2, out);
}

// round 4
// speedup vs baseline: 2.4438x; 1.2846x over previous
#include <cuda_runtime.h>

#define FULLMASK 0xFFFFFFFFu
constexpr int Bb = 4, Nn = 384, Dd = 64;
constexpr int NR = Bb * Nn;

__device__ float g_y2[NR];
__device__ float g_uself[NR * Dd];
__device__ float g_ci[NR * Dd];
__device__ float g_P[NR * Dd];
__device__ float g_gram[(size_t)Bb * Nn * Nn];

__device__ __forceinline__ float wred(float v) {
  #pragma unroll
  for (int o = 16; o > 0; o >>= 1) v += __shfl_xor_sync(FULLMASK, v, o);
  return v;
}
__device__ __forceinline__ float sigm(float x) { return 1.f / (1.f + __expf(-x)); }
__device__ __forceinline__ float silu_(float x) { return x * sigm(x); }
__device__ __forceinline__ float artanh_(float x) {
  x = fminf(x, 1.f - 1e-7f);
  return 0.5f * (log1pf(x) - log1pf(-x));
}
__device__ __forceinline__ float tfa(float x) {   // hw tanh approx
  float y; asm("tanh.approx.f32 %0, %1;" : "=f"(y) : "f"(x)); return y;
}

// ============ k_pre: per-row (y2, uself, P, ci) + gram, 8 rows/block ============
__global__ __launch_bounds__(256)
void k_pre(const float* __restrict__ x,
           const float* __restrict__ att_w1,
           const float* __restrict__ att_b1)
{
  __shared__ float xis[8][64];
  __shared__ float us[8][64];
  __shared__ float xjs[32][65];
  const int tid = threadIdx.x, w = tid >> 5, lane = tid & 31;
  const int ct = blockIdx.x;
  const int b = ct / 48, i0 = (ct % 48) * 8;          // FIXED: 48 groups/batch
  const float* xb = x + (size_t)b * Nn * 64;

  for (int t = tid; t < 512; t += 256)
    xis[t >> 6][t & 63] = xb[(size_t)(i0 + (t >> 6)) * 64 + (t & 63)];
  __syncthreads();

  // per-row scalars + u_self (warp w -> row w), numerics match reference recipe
  {
    const int r = w, gi = b * Nn + i0 + r;
    const float a0 = xis[r][lane], a1 = xis[r][lane + 32];
    const float x2 = wred(a0 * a0 + a1 * a1);
    const float A = 1.f - 2.f * x2 + x2;
    const float Bc = 1.f - x2;
    const float den = fmaxf(1.f - 2.f * x2 + x2 * x2, 1e-15f);
    const float inv = 1.f / den;
    const float s0 = (A * (-a0) + Bc * a0) * inv;
    const float s1 = (A * (-a1) + Bc * a1) * inv;
    const float sn = fmaxf(sqrtf(wred(s0 * s0 + s1 * s1)), 1e-15f);
    const float fac = fmaxf(Bc, 1e-15f);
    const float g = fac * artanh_(sn) / sn;
    us[r][lane] = g * s0; us[r][lane + 32] = g * s1;
    g_uself[(size_t)gi * 64 + lane] = g * s0;
    g_uself[(size_t)gi * 64 + lane + 32] = g * s1;
    if (!lane) g_y2[gi] = x2;
  }
  __syncthreads();

  // P = x@W1a, ci = b1 + uself@W1b : thread (k, row-pair)
  {
    const int k = tid & 63, rp = tid >> 6;     // rows rp, rp+4
    float p0 = 0.f, p1 = 0.f, c0 = att_b1[k], c1v = att_b1[k];
    #pragma unroll 8
    for (int d = 0; d < 64; ++d) {
      const float wa = att_w1[d * 64 + k];
      const float wb = att_w1[(64 + d) * 64 + k];
      p0 = fmaf(xis[rp][d], wa, p0);
      p1 = fmaf(xis[rp + 4][d], wa, p1);
      c0 = fmaf(us[rp][d], wb, c0);
      c1v = fmaf(us[rp + 4][d], wb, c1v);
    }
    const int g0 = b * Nn + i0 + rp, g1 = g0 + 4;
    g_P[(size_t)g0 * 64 + k] = p0; g_P[(size_t)g1 * 64 + k] = p1;
    g_ci[(size_t)g0 * 64 + k] = c0; g_ci[(size_t)g1 * 64 + k] = c1v;
  }

  // gram: xy[i0+ii][j] for all j
  const int ii = tid >> 5, jj = tid & 31;
  for (int jt = 0; jt < 12; ++jt) {
    __syncthreads();
    for (int t = tid; t < 2048; t += 256)
      xjs[t >> 6][t & 63] = xb[(size_t)(jt * 32 + (t >> 6)) * 64 + (t & 63)];
    __syncthreads();
    float acc = 0.f;
    #pragma unroll 16
    for (int d = 0; d < 64; ++d) acc = fmaf(xis[ii][d], xjs[jj][d], acc);
    g_gram[((size_t)(b * Nn) + i0 + ii) * Nn + jt * 32 + jj] = acc;
  }
}

// ============ k_main: 4 rows/block, lane-parallel edges ============
__global__ __launch_bounds__(256)
void k_main(const float* __restrict__ x,
            const int* __restrict__ mask,
            const float* __restrict__ att_w2,
            const float* __restrict__ att_b2,
            const float* __restrict__ mlp_w1,
            const float* __restrict__ mlp_b1,
            const float* __restrict__ mlp_w2,
            const float* __restrict__ mlp_b2,
            float* __restrict__ out)
{
  __shared__ __align__(16) float Pt[64 * 129];        // 33 KB, transposed P tile
  __shared__ float4 cpw[4][64];                       // (ci, Pi, w2, 0)
  __shared__ float wkj[4][Nn];                        // compact att*c2
  __shared__ unsigned short wji[4][Nn];               // compact j index
  __shared__ unsigned char jidx[4][128];
  __shared__ int mcnt[4], mbase[4];
  __shared__ float s1p[8];

  const int tid = threadIdx.x, w = tid >> 5, lane = tid & 31;
  const int ct = blockIdx.x;
  const int b = ct / 96, i0 = (ct % 96) * 4;
  const int r = w & 3;
  const int gi = b * Nn + i0 + r;

  // setup: cpw pack
  {
    const int rr = tid >> 6, k = tid & 63;
    const int gr_ = b * Nn + i0 + rr;
    cpw[rr][k] = make_float4(g_ci[(size_t)gr_ * 64 + k],
                             g_P[(size_t)gr_ * 64 + k], att_w2[k], 0.f);
  }
  if (tid < 4) { mbase[tid] = 0; }
  __syncthreads();

  const float x2i = g_y2[gi];
  const float omx2 = 1.f - x2i;
  const float fac = fmaxf(omx2, 1e-15f);
  const float b2v = att_b2[0];
  float S1 = 0.f;

  const float4* cp4 = cpw[r];
  const float* Pbat = g_P + (size_t)(b * Nn) * 64;

  for (int jt = 0; jt < 3; ++jt) {
    const int j0 = jt * 128;
    __syncthreads();
    // load Pt tile (transposed, pad-129 -> conflict-free STS)
    for (int t = tid; t < 8192; t += 256) {
      const int j = t >> 6, k = t & 63;
      Pt[k * 129 + j] = Pbat[(size_t)(j0 + j) * 64 + k];
    }
    // compaction: warp w<4 -> row w
    if (w < 4) {
      const int* mrow = mask + (size_t)(b * Nn + i0 + w) * Nn + j0;
      int m = 0;
      #pragma unroll
      for (int sub = 0; sub < 4; ++sub) {
        const bool ok = mrow[sub * 32 + lane] != 0;
        const unsigned bal = __ballot_sync(FULLMASK, ok);
        const unsigned pre = bal & ((1u << lane) - 1u);
        if (ok) jidx[w][m + __popc(pre)] = (unsigned char)(sub * 32 + lane);
        m += __popc(bal);
      }
      if (!lane) mcnt[w] = m;
    }
    __syncthreads();

    const int m = mcnt[r];
    const int mb = mbase[r];
    const float* grow = g_gram + (size_t)gi * Nn + j0;
    const float* y2row = g_y2 + b * Nn + j0;

    for (int g = (w >> 2); g * 32 < m; g += 2) {
      const int idx = g * 32 + lane;
      const bool val = idx < m;
      const int jj = val ? jidx[r][idx] : 0;
      float c1 = 0.f, c2 = 0.f;
      if (val) {
        const float xy = grow[jj], y2v = y2row[jj];
        const float A = 1.f - 2.f * xy + y2v;
        const float den = fmaxf(fmaf(x2i, y2v, 1.f - 2.f * xy), 1e-15f);
        const float inv = __frcp_rn(den);
        const float t1 = fmaf(A, x2i, -omx2 * xy);
        const float t2 = fmaf(omx2, y2v, -A * xy);
        float sn = sqrtf(fmaxf(inv * inv * fmaf(A, t1, omx2 * t2), 0.f));
        sn = fminf(fmaxf(sn, 1e-15f), 1.f - 1e-7f);
        const float aos = (sn > 1e-3f)
            ? __fdividef(0.5f * __logf((1.f + sn) * __frcp_rn(1.f - sn)), sn)
            : fmaf(sn * sn, 0.33333334f, 1.f);
        const float gg = fac * aos * inv;
        c1 = -gg * A; c2 = gg * omx2;
      }
      float pr = 0.f;
      #pragma unroll 16
      for (int k = 0; k < 64; ++k) {
        const float4 cp = cp4[k];
        float h = fmaf(c1, cp.y, cp.x);
        h = fmaf(c2, Pt[k * 129 + jj], h);
        const float t = 0.5f * h;
        pr = fmaf(fmaf(t, tfa(t), t), cp.z, pr);   // silu(h)*w2
      }
      const float att = fmaf(0.5f, tfa(0.5f * (pr + b2v)), 0.5f);
      S1 = fmaf(att, c1, S1);
      if (val) {
        wkj[r][mb + idx] = att * c2;
        wji[r][mb + idx] = (unsigned short)(j0 + jj);
      }
    }
    __syncthreads();
    if (tid < 4) mbase[tid] += mcnt[tid];
  }
  // per-warp S1 reduce
  {
    const float s = wred(S1);
    if (!lane) s1p[w] = s;
  }
  __syncthreads();

  float* tailbuf = Pt;   // reuse Pt region
  float* supv = tailbuf;            // [4][64]
  float* hm2  = tailbuf + 256;      // [4][64]
  float* ot   = tailbuf + 512;      // [4][64]

  // support = S1tot*x_i + sum over compact list
  {
    const int i2 = tid >> 6, d = tid & 63;
    const int gr_ = b * Nn + i0 + i2;
    const float* xb = x + (size_t)(b * Nn) * 64;
    const int mt = mbase[i2];
    float acc = 0.f;
    for (int p = 0; p < mt; ++p)
      acc = fmaf(wkj[i2][p], xb[(size_t)wji[i2][p] * 64 + d], acc);
    const float S1t = s1p[i2] + s1p[i2 + 4];
    supv[i2 * 64 + d] = fmaf(S1t, x[(size_t)gr_ * 64 + d], acc);
  }
  __syncthreads();

  // node MLP layer 1
  {
    const int i2 = tid >> 6, k = tid & 63;
    const int gr_ = b * Nn + i0 + i2;
    float acc = mlp_b1[k];
    #pragma unroll 8
    for (int d = 0; d < 64; ++d)
      acc = fmaf(g_uself[(size_t)gr_ * 64 + d], mlp_w1[d * 64 + k], acc);
    #pragma unroll 8
    for (int d = 0; d < 64; ++d)
      acc = fmaf(supv[i2 * 64 + d], mlp_w1[(64 + d) * 64 + k], acc);
    hm2[i2 * 64 + k] = silu_(acc);
  }
  __syncthreads();
  // layer 2 + residual
  {
    const int i2 = tid >> 6, k = tid & 63;
    const int gr_ = b * Nn + i0 + i2;
    float o = mlp_b2[k] + g_uself[(size_t)gr_ * 64 + k];
    #pragma unroll 8
    for (int d = 0; d < 64; ++d)
      o = fmaf(hm2[i2 * 64 + d], mlp_w2[d * 64 + k], o);
    ot[i2 * 64 + k] = o;
  }
  __syncthreads();

  // expmap + proj: warps 0..3 -> rows 0..3
  if (w < 4) {
    const int gr_ = b * Nn + i0 + w;
    const float a0 = x[(size_t)gr_ * 64 + lane], a1 = x[(size_t)gr_ * 64 + lane + 32];
    const float xx2 = g_y2[gr_];
    const float o0 = ot[w * 64 + lane], o1 = ot[w * 64 + lane + 32];
    const float un = fmaxf(sqrtf(wred(o0 * o0 + o1 * o1)), 1e-15f);
    const float lam = 2.f / fmaxf(1.f - xx2, 1e-15f);
    const float th = tanhf(0.5f * lam * un);
    const float sc = th / un;
    const float sec0 = sc * o0, sec1 = sc * o1;
    const float xy = wred(a0 * sec0 + a1 * sec1);
    const float y2 = wred(sec0 * sec0 + sec1 * sec1);
    const float A = 1.f + 2.f * xy + y2;
    const float Bc = 1.f - xx2;
    const float den = fmaxf(1.f + 2.f * xy + xx2 * y2, 1e-15f);
    const float inv = 1.f / den;
    float r0 = (A * a0 + Bc * sec0) * inv;
    float r1 = (A * a1 + Bc * sec1) * inv;
    const float nrm = fmaxf(sqrtf(wred(r0 * r0 + r1 * r1)), 1e-15f);
    if (nrm > 0.996f) { const float s = 0.996f / nrm; r0 *= s; r1 *= s; }
    float* orow = out + (size_t)gr_ * 64;
    orow[lane] = r0; orow[lane + 32] = r1;
  }
}

extern "C" void kernel_launch(void* const* d_in, const int* in_sizes, int n_in,
                              void* d_out, int out_size)
{
  const float* x      = (const float*)d_in[0];
  const int*   mask   = (const int*)d_in[1];
  const float* att_w1 = (const float*)d_in[2];
  const float* att_b1 = (const float*)d_in[3];
  const float* att_w2 = (const float*)d_in[4];
  const float* att_b2 = (const float*)d_in[5];
  const float* mlp_w1 = (const float*)d_in[6];
  const float* mlp_b1 = (const float*)d_in[7];
  const float* mlp_w2 = (const float*)d_in[8];
  const float* mlp_b2 = (const float*)d_in[9];
  float* out = (float*)d_out;

  k_pre<<<Bb * (Nn / 8), 256>>>(x, att_w1, att_b1);
  k_main<<<Bb * (Nn / 4), 256>>>(x, mask, att_w2, att_b2,
                                 mlp_w1, mlp_b1, mlp_w2, mlp_b2, out);
}